// round 14
// baseline (speedup 1.0000x reference)
#include <cuda_runtime.h>
#include <cuda_fp16.h>
#include <cstdint>
#include <math.h>

#define BB 512
#define TT 255
#define DD 128
#define HH 1024
#define GG 4096   // 4*H
#define KC 1152   // D + H
#define NKT 18    // KC/64

#define NCTA 128      // 64 N-blocks x 2 M-blocks, all co-resident
#define MT 256        // M tile
#define NT 64         // N tile

// smem geometry
#define B_ROW_H 1160                          // 1152 + 8 pad halves (stride 2320B = 1 mod 8 slots)
#define B_BYTES (NT * B_ROW_H * 2)            // 148480
#define A_ROW_H 72                            // 64 + 8 pad halves (stride 144B = 1 mod 8 slots)
#define A_STAGE_BYTES (MT * A_ROW_H * 2)      // 36864
#define STAGES 2
#define SMEM_TOTAL (B_BYTES + STAGES * A_STAGE_BYTES)  // 222208
#define EPI_STRIDE 68                         // fp32 gate staging stride (floats)
// S = 256 x 68 floats = 69632 B fits the 2-stage A ring (73728 B). The
// cross-step prefetch (chunk 0 -> stage 0) is issued only AFTER the last S
// read (guarded by the early-arrive __syncthreads). Stage map: chunk c -> c&1.

// ---------------- scratch (device globals: no allocation allowed) ----------
__device__ __align__(16) float  g_a[BB * DD];
__device__ __align__(16) __half g_wh[(size_t)BB * TT * DD];   // w = a*x fp16
__device__ __align__(16) __half g_hbuf[2][BB * HH];           // h ping-pong fp16
__device__ __align__(16) __half g_wcat[(size_t)GG * KC];      // permuted weights fp16
__device__ __align__(16) float  g_bias[GG];                   // permuted bias
// progressive barrier: [mb][quarter] monotonic counters; quarter q covers
// producer CTAs nb = 16q..16q+15 (h units 256q..256q+255).
__device__ unsigned g_sync4[2][4];

__device__ __forceinline__ void cp16(uint32_t smem_dst, const void* gmem_src) {
    asm volatile("cp.async.cg.shared.global [%0], [%1], 16;\n" :: "r"(smem_dst), "l"(gmem_src));
}
__device__ __forceinline__ void cp_commit() { asm volatile("cp.async.commit_group;\n"); }
template <int N> __device__ __forceinline__ void cp_wait() {
    asm volatile("cp.async.wait_group %0;\n" :: "n"(N));
}
__device__ __forceinline__ uint32_t smem_u32(const void* p) {
    uint32_t a;
    asm("{ .reg .u64 t; cvta.to.shared.u64 t, %1; cvt.u32.u64 %0, t; }" : "=r"(a) : "l"(p));
    return a;
}
__device__ __forceinline__ void ldsm4(uint32_t& r0, uint32_t& r1, uint32_t& r2, uint32_t& r3,
                                      uint32_t addr) {
    asm volatile("ldmatrix.sync.aligned.m8n8.x4.shared.b16 {%0,%1,%2,%3}, [%4];"
                 : "=r"(r0), "=r"(r1), "=r"(r2), "=r"(r3) : "r"(addr));
}
__device__ __forceinline__ float tanh_fast(float x) {
    float y;
    asm("tanh.approx.f32 %0, %1;" : "=f"(y) : "f"(x));
    return y;
}
__device__ __forceinline__ float sigmoid_fast(float x) {
    // sigma(x) = 0.5*tanh(x/2) + 0.5  -> single MUFU op
    return fmaf(0.5f, tanh_fast(0.5f * x), 0.5f);
}
__device__ __forceinline__ unsigned ld_acq(const unsigned* p) {
    unsigned v;
    asm volatile("ld.acquire.gpu.global.u32 %0, [%1];" : "=r"(v) : "l"(p));
    return v;
}
__device__ __forceinline__ void red_release_add(unsigned* p, unsigned v) {
    asm volatile("red.release.gpu.global.add.u32 [%0], %1;" :: "l"(p), "r"(v) : "memory");
}

// ---------------- kernel 1: e_x + softmax -> g_a ---------------------------
__global__ void attn_kernel(const float* __restrict__ x, const float* __restrict__ wattn) {
    int b = blockIdx.x, d = threadIdx.x;  // 128 threads
    __shared__ float swx[TT];
    __shared__ float red[8];
    for (int i = d; i < TT; i += DD) swx[i] = wattn[2 * HH + i];
    __syncthreads();
    const float* xb = x + (size_t)b * TT * DD + d;
    float e = 0.f;
#pragma unroll 5
    for (int t = 0; t < TT; t++) e += xb[(size_t)t * DD] * swx[t];
    int lane = d & 31, warp = d >> 5;
    float m = e;
#pragma unroll
    for (int o = 16; o; o >>= 1) m = fmaxf(m, __shfl_xor_sync(0xffffffffu, m, o));
    if (!lane) red[warp] = m;
    __syncthreads();
    m = fmaxf(fmaxf(red[0], red[1]), fmaxf(red[2], red[3]));
    float ex = expf(e - m);
    float s = ex;
#pragma unroll
    for (int o = 16; o; o >>= 1) s += __shfl_xor_sync(0xffffffffu, s, o);
    if (!lane) red[4 + warp] = s;
    __syncthreads();
    s = red[4] + red[5] + red[6] + red[7];
    g_a[b * DD + d] = ex / s;
}

// ---------------- kernel 2: w = a*x -> outw (fp32) + g_wh (fp16) -----------
__global__ void weight_kernel(const float* __restrict__ x, float* __restrict__ outw) {
    size_t n4 = (size_t)BB * TT * DD / 4;
    const float4* x4 = (const float4*)x;
    const float4* a4 = (const float4*)g_a;
    float4* o4 = (float4*)outw;
    __half2* h2 = (__half2*)g_wh;
    for (size_t i = (size_t)blockIdx.x * blockDim.x + threadIdx.x; i < n4;
         i += (size_t)gridDim.x * blockDim.x) {
        size_t b = i / (TT * 32);
        int d4 = (int)(i % 32);
        float4 av = a4[b * 32 + d4];
        float4 xv = x4[i];
        float4 w = make_float4(av.x * xv.x, av.y * xv.y, av.z * xv.z, av.w * xv.w);
        o4[i] = w;
        h2[2 * i]     = __floats2half2_rn(w.x, w.y);
        h2[2 * i + 1] = __floats2half2_rn(w.z, w.w);
    }
}

// ---------------- kernel 3: permuted fp16 weights + bias --------------------
// output col n <-> gate row r = (n&3)*H + (n>>2): 4-col groups = (i,f,g,o) quads
__global__ void prep_kernel(const float* __restrict__ wih, const float* __restrict__ whh,
                            const float* __restrict__ bih, const float* __restrict__ bhh) {
    size_t n = (size_t)GG * KC;
    size_t tid0 = (size_t)blockIdx.x * blockDim.x + threadIdx.x;
    for (size_t i = tid0; i < n; i += (size_t)gridDim.x * blockDim.x) {
        int k = (int)(i % KC);
        int nn = (int)(i / KC);
        int r = (nn & 3) * HH + (nn >> 2);
        float v = (k < DD) ? wih[(size_t)r * DD + k] : whh[(size_t)r * HH + (k - DD)];
        g_wcat[i] = __float2half_rn(v);
    }
    if (tid0 < GG) {
        int r = ((int)tid0 & 3) * HH + ((int)tid0 >> 2);
        g_bias[tid0] = bih[r] + bhh[r];
    }
}

// ---------------- kernel 4: zero h0, sync counters ---------------------------
__global__ void zero_kernel() {
    int i = blockIdx.x * blockDim.x + threadIdx.x;
    if (i < BB * HH) g_hbuf[0][i] = __float2half(0.f);
    if (i < 8) ((unsigned*)g_sync4)[i] = 0;
}

// ---------------- kernel 5: persistent fused LSTM ---------------------------
// 128 CTAs x 256 threads; B resident; 64-wide K-chunks; c-state in registers;
// tail prefetch; progressive quarter-barriers (waits at c=1,5,9,13).
__global__ __launch_bounds__(256) void persistent_lstm(float* __restrict__ outh) {
    extern __shared__ char smraw[];
    float* S = (float*)(smraw + B_BYTES);          // epilogue staging (A ring)
    uint32_t smem_base = smem_u32(smraw);
    uint32_t a_base = smem_base + B_BYTES;

    int tid = threadIdx.x;
    int warp = tid >> 5, lane = tid & 31;
    int wn = warp & 1, wm = warp >> 1;             // 2 warps N x 4 warps M
    int bx = blockIdx.x;
    int mb = bx >> 6, nb = bx & 63;
    int bm0 = mb * MT, bn0 = nb * NT;

    // ---- load resident B slab: 64 x 1152 halves -----------------------------
    for (int i = tid; i < NT * (KC / 8); i += 256) {
        int n = i / (KC / 8), kc = i % (KC / 8);
        cp16(smem_base + n * (B_ROW_H * 2) + kc * 16,
             g_wcat + (size_t)(bn0 + n) * KC + kc * 8);
    }
    cp_commit();

    // ---- per-thread ldmatrix lane offsets (bytes) ----------------------------
    int arow = (lane & 7) + ((lane >> 3) & 1) * 8;
    int acol = ((lane >> 4) & 1) * 8;
    uint32_t a_lane_off = (uint32_t)(((wm * 64 + arow) * A_ROW_H + acol) * 2);
    int brow = (lane & 7) + ((lane >> 4) & 1) * 8;
    int bcol = ((lane >> 3) & 1) * 8;
    uint32_t b_lane_base = smem_base + (uint32_t)(((wn * 32 + brow) * B_ROW_H + bcol) * 2);

    // ---- LSTM c-state in registers; per-thread constants ---------------------
    float creg[16];
#pragma unroll
    for (int i = 0; i < 16; i++) creg[i] = 0.f;
    int u = tid & 15;
    int U = nb * 16 + u;
    float4 bi = *(const float4*)&g_bias[bn0 + 4 * u];   // step-invariant
    unsigned* my_arrive = &g_sync4[mb][nb >> 4];

    // A chunk loader: 256x64 halves into stage c&1; tt selects timestep
    auto load_chunk = [&](int tt, int c, const __half* hinp) {
        int ks = c * 64;
        uint32_t ab = a_base + (uint32_t)(c & 1) * A_STAGE_BYTES;
#pragma unroll
        for (int i = 0; i < 8; i++) {
            int o = tid + i * 256;       // 0..2047
            int r = o >> 3, cc = o & 7;  // row, 16B chunk within row
            const __half* src = (ks < DD)
                ? g_wh + ((size_t)(bm0 + r) * TT + tt) * DD + ks + cc * 8
                : hinp + (size_t)(bm0 + r) * HH + (ks - DD) + cc * 8;
            cp16(ab + r * (A_ROW_H * 2) + cc * 16, src);
        }
        cp_commit();
    };

    for (int t = 0; t < TT; t++) {
        const __half* hin = g_hbuf[t & 1];
        __half* hout = g_hbuf[(t + 1) & 1];

        // chunk 0 already prefetched during previous step's tail (t>0)
        if (t == 0) load_chunk(0, 0, hin);

        float acc[4][4][4];
#pragma unroll
        for (int i = 0; i < 4; i++)
#pragma unroll
            for (int j = 0; j < 4; j++)
#pragma unroll
                for (int r = 0; r < 4; r++) acc[i][j][r] = 0.f;

        for (int c = 0; c < NKT; c++) {
            cp_wait<0>();        // chunk c resident (only group outstanding)
            __syncthreads();
            // issue chunk c+1 into the opposite stage (chunk c-1's, consumed).
            // progressive gating: chunk cc=c+1 (cc>=2) reads h units
            // 64(cc-2)..64(cc-2)+63 from producer CTAs 4(cc-2)..4(cc-2)+3;
            // quarter q=(cc-2)>>2 must have all 16 CTAs arrived t times.
            // Waits land at c=1,5,9,13 -- each hidden under ~4 chunks compute.
            if (c + 1 < NKT) {
                if (t > 0 && c >= 1 && c <= 13 && ((c - 1) & 3) == 0) {
                    int q = (c - 1) >> 2;
                    if (tid == 0)
                        while (ld_acq(&g_sync4[mb][q]) < 16u * (unsigned)t) {}
                    __syncthreads();
                }
                load_chunk(t, c + 1, hin);
            }

            uint32_t ab = a_base + (uint32_t)(c & 1) * A_STAGE_BYTES + a_lane_off;
            uint32_t bb = b_lane_base + c * 128;  // 64 cols * 2B per chunk
#pragma unroll
            for (int kk = 0; kk < 4; kk++) {
                uint32_t af[4][4], bf[4][2];
#pragma unroll
                for (int mt = 0; mt < 4; mt++)
                    ldsm4(af[mt][0], af[mt][1], af[mt][2], af[mt][3],
                          ab + mt * (16 * A_ROW_H * 2) + kk * 32);
#pragma unroll
                for (int p = 0; p < 2; p++)
                    ldsm4(bf[2 * p][0], bf[2 * p][1], bf[2 * p + 1][0], bf[2 * p + 1][1],
                          bb + p * (16 * B_ROW_H * 2) + kk * 32);
#pragma unroll
                for (int mt = 0; mt < 4; mt++)
#pragma unroll
                    for (int nt = 0; nt < 4; nt++)
                        asm volatile(
                            "mma.sync.aligned.m16n8k16.row.col.f32.f16.f16.f32 "
                            "{%0,%1,%2,%3}, {%4,%5,%6,%7}, {%8,%9}, {%0,%1,%2,%3};"
                            : "+f"(acc[mt][nt][0]), "+f"(acc[mt][nt][1]),
                              "+f"(acc[mt][nt][2]), "+f"(acc[mt][nt][3])
                            : "r"(af[mt][0]), "r"(af[mt][1]), "r"(af[mt][2]), "r"(af[mt][3]),
                              "r"(bf[nt][0]), "r"(bf[nt][1]));
            }
        }
        __syncthreads();  // all MMA fragment reads done; A ring reusable as S

        // ---- epilogue phase 1: stage gates to smem (fp32) -------------------
#pragma unroll
        for (int mt = 0; mt < 4; mt++) {
            int r0 = wm * 64 + mt * 16 + (lane >> 2);
#pragma unroll
            for (int nt = 0; nt < 4; nt++) {
                int c0 = wn * 32 + nt * 8 + ((lane & 3) << 1);
                *(float2*)&S[r0 * EPI_STRIDE + c0] =
                    make_float2(acc[mt][nt][0], acc[mt][nt][1]);
                *(float2*)&S[(r0 + 8) * EPI_STRIDE + c0] =
                    make_float2(acc[mt][nt][2], acc[mt][nt][3]);
            }
        }
        __syncthreads();

        // ---- epilogue phase 2: LSTM update (c in regs), store h first -------
        float hnv[16];
#pragma unroll
        for (int i = 0; i < 16; i++) {
            int row = (tid >> 4) + i * 16;
            float4 g = *(const float4*)&S[row * EPI_STRIDE + 4 * u];
            float si = sigmoid_fast(g.x + bi.x);
            float sf = sigmoid_fast(g.y + bi.y);
            float gg = tanh_fast(g.z + bi.z);
            float so = sigmoid_fast(g.w + bi.w);
            float cn = sf * creg[i] + si * gg;
            float hn = so * tanh_fast(cn);
            creg[i] = cn;
            hnv[i] = hn;
            hout[(size_t)(bm0 + row) * HH + U] = __float2half_rn(hn);
        }

        // ---- early arrive (release atomic) + cross-step prefetch -------------
        if (t + 1 < TT) {
            __syncthreads();   // all h writes issued; ALL S reads done
            // release-atomic publishes this CTA's h stores (happens-before via
            // the syncthreads) to the consumers' ld.acquire spins.
            if (tid == 0) red_release_add(my_arrive, 1u);
            // prefetch next step's w-chunk 0 into stage 0 (safe: S reads done);
            // overlaps output stores + other CTAs' arrivals.
            load_chunk(t + 1, 0, hin);
        }
#pragma unroll
        for (int i = 0; i < 16; i++) {
            int row = (tid >> 4) + i * 16;
            outh[((size_t)(bm0 + row) * TT + t) * HH + U] = hnv[i];
        }
    }
}

// ---------------- launch ----------------------------------------------------
extern "C" void kernel_launch(void* const* d_in, const int* in_sizes, int n_in,
                              void* d_out, int out_size) {
    (void)in_sizes; (void)n_in; (void)out_size;
    const float* x     = (const float*)d_in[0];
    const float* wattn = (const float*)d_in[1];
    // d_in[2] = b_attn: irrelevant (softmax shift invariance)
    const float* wih   = (const float*)d_in[3];
    const float* whh   = (const float*)d_in[4];
    const float* bih   = (const float*)d_in[5];
    const float* bhh   = (const float*)d_in[6];

    float* out  = (float*)d_out;
    float* outw = out;                               // (B, T, D)
    float* outh = out + (size_t)BB * TT * DD;        // (B, T, H)

    cudaFuncSetAttribute(persistent_lstm, cudaFuncAttributeMaxDynamicSharedMemorySize,
                         SMEM_TOTAL);

    attn_kernel<<<BB, DD>>>(x, wattn);
    weight_kernel<<<2048, 256>>>(x, outw);
    prep_kernel<<<2048, 256>>>(wih, whh, bih, bhh);
    zero_kernel<<<(BB * HH + 255) / 256, 256>>>();

    persistent_lstm<<<NCTA, 256, SMEM_TOTAL>>>(outh);
}

// round 15
// speedup vs baseline: 1.0143x; 1.0143x over previous
#include <cuda_runtime.h>
#include <cuda_fp16.h>
#include <cstdint>
#include <math.h>

#define BB 512
#define TT 255
#define DD 128
#define HH 1024
#define GG 4096   // 4*H
#define KC 1152   // D + H
#define NKT 18    // KC/64

#define NCTA 128      // 64 N-blocks x 2 M-blocks, all co-resident
#define MT 256        // M tile
#define NT 64         // N tile

// smem geometry
#define B_ROW_H 1160                          // 1152 + 8 pad halves (stride 2320B = 1 mod 8 slots)
#define B_BYTES (NT * B_ROW_H * 2)            // 148480
#define A_ROW_H 72                            // 64 + 8 pad halves (stride 144B = 1 mod 8 slots)
#define A_STAGE_BYTES (MT * A_ROW_H * 2)      // 36864
#define STAGES 2
#define SMEM_TOTAL (B_BYTES + STAGES * A_STAGE_BYTES)  // 222208
#define EPI_STRIDE 68                         // fp32 gate staging stride (floats)
// S = 256 x 68 floats = 69632 B fits the 2-stage A ring (73728 B). The
// cross-step prefetch (chunk 0 -> stage 0) is issued only AFTER the last S
// read (guarded by the early-arrive __syncthreads). Stage map: chunk c -> c&1.

// ---------------- scratch (device globals: no allocation allowed) ----------
__device__ __align__(16) __half g_wh[(size_t)BB * TT * DD];   // w = a*x fp16
__device__ __align__(16) __half g_hbuf[2][BB * HH];           // h ping-pong fp16
__device__ __align__(16) __half g_wcat[(size_t)GG * KC];      // permuted weights fp16
__device__ __align__(16) float  g_bias[GG];                   // permuted bias
__device__ unsigned g_sync[2];                // per-M-group monotonic step counter

__device__ __forceinline__ void cp16(uint32_t smem_dst, const void* gmem_src) {
    asm volatile("cp.async.cg.shared.global [%0], [%1], 16;\n" :: "r"(smem_dst), "l"(gmem_src));
}
__device__ __forceinline__ void cp_commit() { asm volatile("cp.async.commit_group;\n"); }
template <int N> __device__ __forceinline__ void cp_wait() {
    asm volatile("cp.async.wait_group %0;\n" :: "n"(N));
}
__device__ __forceinline__ uint32_t smem_u32(const void* p) {
    uint32_t a;
    asm("{ .reg .u64 t; cvta.to.shared.u64 t, %1; cvt.u32.u64 %0, t; }" : "=r"(a) : "l"(p));
    return a;
}
__device__ __forceinline__ void ldsm4(uint32_t& r0, uint32_t& r1, uint32_t& r2, uint32_t& r3,
                                      uint32_t addr) {
    asm volatile("ldmatrix.sync.aligned.m8n8.x4.shared.b16 {%0,%1,%2,%3}, [%4];"
                 : "=r"(r0), "=r"(r1), "=r"(r2), "=r"(r3) : "r"(addr));
}
__device__ __forceinline__ float tanh_fast(float x) {
    float y;
    asm("tanh.approx.f32 %0, %1;" : "=f"(y) : "f"(x));
    return y;
}
__device__ __forceinline__ float sigmoid_fast(float x) {
    // sigma(x) = 0.5*tanh(x/2) + 0.5  -> single MUFU op
    return fmaf(0.5f, tanh_fast(0.5f * x), 0.5f);
}
__device__ __forceinline__ unsigned ld_acq(const unsigned* p) {
    unsigned v;
    asm volatile("ld.acquire.gpu.global.u32 %0, [%1];" : "=r"(v) : "l"(p));
    return v;
}
__device__ __forceinline__ void red_release_add(unsigned* p, unsigned v) {
    asm volatile("red.release.gpu.global.add.u32 [%0], %1;" :: "l"(p), "r"(v) : "memory");
}

// ---------------- kernel 1: fused e_x + softmax + w = a*x -------------------
// One block per batch row. x[b] (130 KB) is read for e_x, then re-read L1-hot
// for the weighted output -- saves a full DRAM pass vs separate kernels.
__global__ void attn_weight_kernel(const float* __restrict__ x,
                                   const float* __restrict__ wattn,
                                   float* __restrict__ outw) {
    int b = blockIdx.x, d = threadIdx.x;  // 128 threads
    __shared__ float swx[TT];
    __shared__ float red[8];
    for (int i = d; i < TT; i += DD) swx[i] = wattn[2 * HH + i];
    __syncthreads();
    const float* xb = x + (size_t)b * TT * DD + d;
    float e = 0.f;
#pragma unroll 5
    for (int t = 0; t < TT; t++) e += xb[(size_t)t * DD] * swx[t];
    int lane = d & 31, warp = d >> 5;
    float m = e;
#pragma unroll
    for (int o = 16; o; o >>= 1) m = fmaxf(m, __shfl_xor_sync(0xffffffffu, m, o));
    if (!lane) red[warp] = m;
    __syncthreads();
    m = fmaxf(fmaxf(red[0], red[1]), fmaxf(red[2], red[3]));
    float ex = expf(e - m);
    float s = ex;
#pragma unroll
    for (int o = 16; o; o >>= 1) s += __shfl_xor_sync(0xffffffffu, s, o);
    if (!lane) red[4 + warp] = s;
    __syncthreads();
    s = red[4] + red[5] + red[6] + red[7];
    float a = ex / s;

    // weighted input: same arithmetic as the old weight_kernel (w = a*x fp32,
    // then rn to half for the GEMM shadow copy)
    float* ob = outw + (size_t)b * TT * DD + d;
    __half* hb = g_wh + (size_t)b * TT * DD + d;
#pragma unroll 5
    for (int t = 0; t < TT; t++) {
        float w = a * xb[(size_t)t * DD];
        ob[(size_t)t * DD] = w;
        hb[(size_t)t * DD] = __float2half_rn(w);
    }
}

// ---------------- kernel 2: permuted fp16 weights + bias --------------------
// output col n <-> gate row r = (n&3)*H + (n>>2): 4-col groups = (i,f,g,o) quads
__global__ void prep_kernel(const float* __restrict__ wih, const float* __restrict__ whh,
                            const float* __restrict__ bih, const float* __restrict__ bhh) {
    size_t n = (size_t)GG * KC;
    size_t tid0 = (size_t)blockIdx.x * blockDim.x + threadIdx.x;
    for (size_t i = tid0; i < n; i += (size_t)gridDim.x * blockDim.x) {
        int k = (int)(i % KC);
        int nn = (int)(i / KC);
        int r = (nn & 3) * HH + (nn >> 2);
        float v = (k < DD) ? wih[(size_t)r * DD + k] : whh[(size_t)r * HH + (k - DD)];
        g_wcat[i] = __float2half_rn(v);
    }
    if (tid0 < GG) {
        int r = ((int)tid0 & 3) * HH + ((int)tid0 >> 2);
        g_bias[tid0] = bih[r] + bhh[r];
    }
}

// ---------------- kernel 3: zero h0, sync counters ---------------------------
__global__ void zero_kernel() {
    int i = blockIdx.x * blockDim.x + threadIdx.x;
    if (i < BB * HH) g_hbuf[0][i] = __float2half(0.f);
    if (i < 2) g_sync[i] = 0;
}

// ---------------- kernel 4: persistent fused LSTM ---------------------------
// 128 CTAs x 256 threads; B resident; 64-wide K-chunks (18 syncs/step);
// c-state in registers; tail prefetch; release-atomic arrive / acquire wait.
__global__ __launch_bounds__(256) void persistent_lstm(float* __restrict__ outh) {
    extern __shared__ char smraw[];
    float* S = (float*)(smraw + B_BYTES);          // epilogue staging (A ring)
    uint32_t smem_base = smem_u32(smraw);
    uint32_t a_base = smem_base + B_BYTES;

    int tid = threadIdx.x;
    int warp = tid >> 5, lane = tid & 31;
    int wn = warp & 1, wm = warp >> 1;             // 2 warps N x 4 warps M
    int bx = blockIdx.x;
    int mb = bx >> 6, nb = bx & 63;
    int bm0 = mb * MT, bn0 = nb * NT;

    // ---- load resident B slab: 64 x 1152 halves -----------------------------
    for (int i = tid; i < NT * (KC / 8); i += 256) {
        int n = i / (KC / 8), kc = i % (KC / 8);
        cp16(smem_base + n * (B_ROW_H * 2) + kc * 16,
             g_wcat + (size_t)(bn0 + n) * KC + kc * 8);
    }
    cp_commit();

    // ---- per-thread ldmatrix lane offsets (bytes) ----------------------------
    int arow = (lane & 7) + ((lane >> 3) & 1) * 8;
    int acol = ((lane >> 4) & 1) * 8;
    uint32_t a_lane_off = (uint32_t)(((wm * 64 + arow) * A_ROW_H + acol) * 2);
    int brow = (lane & 7) + ((lane >> 4) & 1) * 8;
    int bcol = ((lane >> 3) & 1) * 8;
    uint32_t b_lane_base = smem_base + (uint32_t)(((wn * 32 + brow) * B_ROW_H + bcol) * 2);

    // ---- LSTM c-state in registers; per-thread constants ---------------------
    float creg[16];
#pragma unroll
    for (int i = 0; i < 16; i++) creg[i] = 0.f;
    int u = tid & 15;
    int U = nb * 16 + u;
    float4 bi = *(const float4*)&g_bias[bn0 + 4 * u];   // step-invariant

    // A chunk loader: 256x64 halves into stage c&1; tt selects timestep
    auto load_chunk = [&](int tt, int c, const __half* hinp) {
        int ks = c * 64;
        uint32_t ab = a_base + (uint32_t)(c & 1) * A_STAGE_BYTES;
#pragma unroll
        for (int i = 0; i < 8; i++) {
            int o = tid + i * 256;       // 0..2047
            int r = o >> 3, cc = o & 7;  // row, 16B chunk within row
            const __half* src = (ks < DD)
                ? g_wh + ((size_t)(bm0 + r) * TT + tt) * DD + ks + cc * 8
                : hinp + (size_t)(bm0 + r) * HH + (ks - DD) + cc * 8;
            cp16(ab + r * (A_ROW_H * 2) + cc * 16, src);
        }
        cp_commit();
    };

    for (int t = 0; t < TT; t++) {
        const __half* hin = g_hbuf[t & 1];
        __half* hout = g_hbuf[(t + 1) & 1];

        // chunk 0 already prefetched during previous step's tail (t>0)
        if (t == 0) load_chunk(0, 0, hin);

        float acc[4][4][4];
#pragma unroll
        for (int i = 0; i < 4; i++)
#pragma unroll
            for (int j = 0; j < 4; j++)
#pragma unroll
                for (int r = 0; r < 4; r++) acc[i][j][r] = 0.f;

        for (int c = 0; c < NKT; c++) {
            cp_wait<0>();        // chunk c resident (only group outstanding)
            __syncthreads();
            // issue chunk c+1 into the opposite stage (chunk c-1's, consumed).
            // first h-dependent chunk (2) issued at c==1: wait for all
            // producers of h[t-1] here, hidden under chunk-0 compute.
            if (c + 1 < NKT) {
                if (c == 1 && t > 0) {
                    if (tid == 0)
                        while (ld_acq(&g_sync[mb]) < 64u * (unsigned)t) {}
                    __syncthreads();
                }
                load_chunk(t, c + 1, hin);
            }

            uint32_t ab = a_base + (uint32_t)(c & 1) * A_STAGE_BYTES + a_lane_off;
            uint32_t bb = b_lane_base + c * 128;  // 64 cols * 2B per chunk
#pragma unroll
            for (int kk = 0; kk < 4; kk++) {
                uint32_t af[4][4], bf[4][2];
#pragma unroll
                for (int mt = 0; mt < 4; mt++)
                    ldsm4(af[mt][0], af[mt][1], af[mt][2], af[mt][3],
                          ab + mt * (16 * A_ROW_H * 2) + kk * 32);
#pragma unroll
                for (int p = 0; p < 2; p++)
                    ldsm4(bf[2 * p][0], bf[2 * p][1], bf[2 * p + 1][0], bf[2 * p + 1][1],
                          bb + p * (16 * B_ROW_H * 2) + kk * 32);
#pragma unroll
                for (int mt = 0; mt < 4; mt++)
#pragma unroll
                    for (int nt = 0; nt < 4; nt++)
                        asm volatile(
                            "mma.sync.aligned.m16n8k16.row.col.f32.f16.f16.f32 "
                            "{%0,%1,%2,%3}, {%4,%5,%6,%7}, {%8,%9}, {%0,%1,%2,%3};"
                            : "+f"(acc[mt][nt][0]), "+f"(acc[mt][nt][1]),
                              "+f"(acc[mt][nt][2]), "+f"(acc[mt][nt][3])
                            : "r"(af[mt][0]), "r"(af[mt][1]), "r"(af[mt][2]), "r"(af[mt][3]),
                              "r"(bf[nt][0]), "r"(bf[nt][1]));
            }
        }
        __syncthreads();  // all MMA fragment reads done; A ring reusable as S

        // ---- epilogue phase 1: stage gates to smem (fp32) -------------------
#pragma unroll
        for (int mt = 0; mt < 4; mt++) {
            int r0 = wm * 64 + mt * 16 + (lane >> 2);
#pragma unroll
            for (int nt = 0; nt < 4; nt++) {
                int c0 = wn * 32 + nt * 8 + ((lane & 3) << 1);
                *(float2*)&S[r0 * EPI_STRIDE + c0] =
                    make_float2(acc[mt][nt][0], acc[mt][nt][1]);
                *(float2*)&S[(r0 + 8) * EPI_STRIDE + c0] =
                    make_float2(acc[mt][nt][2], acc[mt][nt][3]);
            }
        }
        __syncthreads();

        // ---- epilogue phase 2: LSTM update (c in regs), store h first -------
        float hnv[16];
#pragma unroll
        for (int i = 0; i < 16; i++) {
            int row = (tid >> 4) + i * 16;
            float4 g = *(const float4*)&S[row * EPI_STRIDE + 4 * u];
            float si = sigmoid_fast(g.x + bi.x);
            float sf = sigmoid_fast(g.y + bi.y);
            float gg = tanh_fast(g.z + bi.z);
            float so = sigmoid_fast(g.w + bi.w);
            float cn = sf * creg[i] + si * gg;
            float hn = so * tanh_fast(cn);
            creg[i] = cn;
            hnv[i] = hn;
            hout[(size_t)(bm0 + row) * HH + U] = __float2half_rn(hn);
        }

        // ---- early arrive (release atomic) + cross-step prefetch -------------
        if (t + 1 < TT) {
            __syncthreads();   // all h writes issued; ALL S reads done
            // release-atomic publishes this CTA's h stores (happens-before via
            // the syncthreads) to the consumers' ld.acquire spins.
            if (tid == 0) red_release_add(&g_sync[mb], 1u);
            // prefetch next step's w-chunk 0 into stage 0 (safe: S reads done);
            // overlaps output stores + other CTAs' arrivals.
            load_chunk(t + 1, 0, hin);
        }
#pragma unroll
        for (int i = 0; i < 16; i++) {
            int row = (tid >> 4) + i * 16;
            outh[((size_t)(bm0 + row) * TT + t) * HH + U] = hnv[i];
        }
    }
}

// ---------------- launch ----------------------------------------------------
extern "C" void kernel_launch(void* const* d_in, const int* in_sizes, int n_in,
                              void* d_out, int out_size) {
    (void)in_sizes; (void)n_in; (void)out_size;
    const float* x     = (const float*)d_in[0];
    const float* wattn = (const float*)d_in[1];
    // d_in[2] = b_attn: irrelevant (softmax shift invariance)
    const float* wih   = (const float*)d_in[3];
    const float* whh   = (const float*)d_in[4];
    const float* bih   = (const float*)d_in[5];
    const float* bhh   = (const float*)d_in[6];

    float* out  = (float*)d_out;
    float* outw = out;                               // (B, T, D)
    float* outh = out + (size_t)BB * TT * DD;        // (B, T, H)

    cudaFuncSetAttribute(persistent_lstm, cudaFuncAttributeMaxDynamicSharedMemorySize,
                         SMEM_TOTAL);

    attn_weight_kernel<<<BB, DD>>>(x, wattn, outw);
    prep_kernel<<<2048, 256>>>(wih, whh, bih, bhh);
    zero_kernel<<<(BB * HH + 255) / 256, 256>>>();

    persistent_lstm<<<NCTA, 256, SMEM_TOTAL>>>(outh);
}

// round 16
// speedup vs baseline: 1.1278x; 1.1119x over previous
#include <cuda_runtime.h>
#include <cuda_fp16.h>
#include <cstdint>
#include <math.h>

#define BB 512
#define TT 255
#define DD 128
#define HH 1024
#define GG 4096   // 4*H
#define KC 1152   // D + H
#define NKT 18    // KC/64

#define NCTA 128      // 64 N-blocks x 2 M-blocks, all co-resident
#define MT 256        // M tile
#define NT 64         // N tile
#define NTHR 512      // 16 warps: 2 N-groups x 8 M-groups (4 warps/SMSP)

// smem geometry
#define B_ROW_H 1160                          // 1152 + 8 pad halves (stride 2320B = 1 mod 8 slots)
#define B_BYTES (NT * B_ROW_H * 2)            // 148480
#define A_ROW_H 72                            // 64 + 8 pad halves (stride 144B = 1 mod 8 slots)
#define A_STAGE_BYTES (MT * A_ROW_H * 2)      // 36864
#define STAGES 2
#define SMEM_TOTAL (B_BYTES + STAGES * A_STAGE_BYTES)  // 222208
#define EPI_STRIDE 68                         // fp32 gate staging stride (floats)
// S = 256 x 68 floats = 69632 B fits the 2-stage A ring (73728 B). The
// cross-step prefetch (chunk 0 -> stage 0) is issued only AFTER the last S
// read (guarded by the early-arrive __syncthreads). Stage map: chunk c -> c&1.

// ---------------- scratch (device globals: no allocation allowed) ----------
__device__ __align__(16) __half g_wh[(size_t)BB * TT * DD];   // w = a*x fp16
__device__ __align__(16) __half g_hbuf[2][BB * HH];           // h ping-pong fp16
__device__ __align__(16) __half g_wcat[(size_t)GG * KC];      // permuted weights fp16
__device__ __align__(16) float  g_bias[GG];                   // permuted bias
__device__ unsigned g_sync[2];                // per-M-group monotonic step counter

__device__ __forceinline__ void cp16(uint32_t smem_dst, const void* gmem_src) {
    asm volatile("cp.async.cg.shared.global [%0], [%1], 16;\n" :: "r"(smem_dst), "l"(gmem_src));
}
__device__ __forceinline__ void cp_commit() { asm volatile("cp.async.commit_group;\n"); }
template <int N> __device__ __forceinline__ void cp_wait() {
    asm volatile("cp.async.wait_group %0;\n" :: "n"(N));
}
__device__ __forceinline__ uint32_t smem_u32(const void* p) {
    uint32_t a;
    asm("{ .reg .u64 t; cvta.to.shared.u64 t, %1; cvt.u32.u64 %0, t; }" : "=r"(a) : "l"(p));
    return a;
}
__device__ __forceinline__ void ldsm4(uint32_t& r0, uint32_t& r1, uint32_t& r2, uint32_t& r3,
                                      uint32_t addr) {
    asm volatile("ldmatrix.sync.aligned.m8n8.x4.shared.b16 {%0,%1,%2,%3}, [%4];"
                 : "=r"(r0), "=r"(r1), "=r"(r2), "=r"(r3) : "r"(addr));
}
__device__ __forceinline__ float tanh_fast(float x) {
    float y;
    asm("tanh.approx.f32 %0, %1;" : "=f"(y) : "f"(x));
    return y;
}
__device__ __forceinline__ float sigmoid_fast(float x) {
    // sigma(x) = 0.5*tanh(x/2) + 0.5  -> single MUFU op
    return fmaf(0.5f, tanh_fast(0.5f * x), 0.5f);
}
__device__ __forceinline__ unsigned ld_acq(const unsigned* p) {
    unsigned v;
    asm volatile("ld.acquire.gpu.global.u32 %0, [%1];" : "=r"(v) : "l"(p));
    return v;
}
__device__ __forceinline__ void red_release_add(unsigned* p, unsigned v) {
    asm volatile("red.release.gpu.global.add.u32 [%0], %1;" :: "l"(p), "r"(v) : "memory");
}

// ---------------- kernel 1: fused e_x + softmax + w = a*x -------------------
__global__ void attn_weight_kernel(const float* __restrict__ x,
                                   const float* __restrict__ wattn,
                                   float* __restrict__ outw) {
    int b = blockIdx.x, d = threadIdx.x;  // 128 threads
    __shared__ float swx[TT];
    __shared__ float red[8];
    for (int i = d; i < TT; i += DD) swx[i] = wattn[2 * HH + i];
    __syncthreads();
    const float* xb = x + (size_t)b * TT * DD + d;
    float e = 0.f;
#pragma unroll 5
    for (int t = 0; t < TT; t++) e += xb[(size_t)t * DD] * swx[t];
    int lane = d & 31, warp = d >> 5;
    float m = e;
#pragma unroll
    for (int o = 16; o; o >>= 1) m = fmaxf(m, __shfl_xor_sync(0xffffffffu, m, o));
    if (!lane) red[warp] = m;
    __syncthreads();
    m = fmaxf(fmaxf(red[0], red[1]), fmaxf(red[2], red[3]));
    float ex = expf(e - m);
    float s = ex;
#pragma unroll
    for (int o = 16; o; o >>= 1) s += __shfl_xor_sync(0xffffffffu, s, o);
    if (!lane) red[4 + warp] = s;
    __syncthreads();
    s = red[4] + red[5] + red[6] + red[7];
    float a = ex / s;

    float* ob = outw + (size_t)b * TT * DD + d;
    __half* hb = g_wh + (size_t)b * TT * DD + d;
#pragma unroll 5
    for (int t = 0; t < TT; t++) {
        float w = a * xb[(size_t)t * DD];
        ob[(size_t)t * DD] = w;
        hb[(size_t)t * DD] = __float2half_rn(w);
    }
}

// ---------------- kernel 2: permuted fp16 weights + bias --------------------
// output col n <-> gate row r = (n&3)*H + (n>>2): 4-col groups = (i,f,g,o) quads
__global__ void prep_kernel(const float* __restrict__ wih, const float* __restrict__ whh,
                            const float* __restrict__ bih, const float* __restrict__ bhh) {
    size_t n = (size_t)GG * KC;
    size_t tid0 = (size_t)blockIdx.x * blockDim.x + threadIdx.x;
    for (size_t i = tid0; i < n; i += (size_t)gridDim.x * blockDim.x) {
        int k = (int)(i % KC);
        int nn = (int)(i / KC);
        int r = (nn & 3) * HH + (nn >> 2);
        float v = (k < DD) ? wih[(size_t)r * DD + k] : whh[(size_t)r * HH + (k - DD)];
        g_wcat[i] = __float2half_rn(v);
    }
    if (tid0 < GG) {
        int r = ((int)tid0 & 3) * HH + ((int)tid0 >> 2);
        g_bias[tid0] = bih[r] + bhh[r];
    }
}

// ---------------- kernel 3: zero h0, sync counters ---------------------------
__global__ void zero_kernel() {
    int i = blockIdx.x * blockDim.x + threadIdx.x;
    if (i < BB * HH) g_hbuf[0][i] = __float2half(0.f);
    if (i < 2) g_sync[i] = 0;
}

// ---------------- kernel 4: persistent fused LSTM ---------------------------
// 128 CTAs x 512 threads (16 warps, 2N x 8M, 4 warps/SMSP for latency hiding);
// B resident; 64-wide K-chunks; c-state in registers; tail prefetch;
// release-atomic arrive / acquire-spin late wait.
__global__ __launch_bounds__(NTHR, 1) void persistent_lstm(float* __restrict__ outh) {
    extern __shared__ char smraw[];
    float* S = (float*)(smraw + B_BYTES);          // epilogue staging (A ring)
    uint32_t smem_base = smem_u32(smraw);
    uint32_t a_base = smem_base + B_BYTES;

    int tid = threadIdx.x;
    int warp = tid >> 5, lane = tid & 31;
    int wn = warp & 1, wm = warp >> 1;             // 2 warps N x 8 warps M
    int bx = blockIdx.x;
    int mb = bx >> 6, nb = bx & 63;
    int bm0 = mb * MT, bn0 = nb * NT;

    // ---- load resident B slab: 64 x 1152 halves -----------------------------
    for (int i = tid; i < NT * (KC / 8); i += NTHR) {
        int n = i / (KC / 8), kc = i % (KC / 8);
        cp16(smem_base + n * (B_ROW_H * 2) + kc * 16,
             g_wcat + (size_t)(bn0 + n) * KC + kc * 8);
    }
    cp_commit();

    // ---- per-thread ldmatrix lane offsets (bytes) ----------------------------
    int arow = (lane & 7) + ((lane >> 3) & 1) * 8;
    int acol = ((lane >> 4) & 1) * 8;
    uint32_t a_lane_off = (uint32_t)(((wm * 32 + arow) * A_ROW_H + acol) * 2);
    int brow = (lane & 7) + ((lane >> 4) & 1) * 8;
    int bcol = ((lane >> 3) & 1) * 8;
    uint32_t b_lane_base = smem_base + (uint32_t)(((wn * 32 + brow) * B_ROW_H + bcol) * 2);

    // ---- LSTM c-state in registers; per-thread constants ---------------------
    float creg[8];
#pragma unroll
    for (int i = 0; i < 8; i++) creg[i] = 0.f;
    int u = tid & 15;
    int U = nb * 16 + u;
    float4 bi = *(const float4*)&g_bias[bn0 + 4 * u];   // step-invariant

    // A chunk loader: 256x64 halves into stage c&1; tt selects timestep
    auto load_chunk = [&](int tt, int c, const __half* hinp) {
        int ks = c * 64;
        uint32_t ab = a_base + (uint32_t)(c & 1) * A_STAGE_BYTES;
#pragma unroll
        for (int i = 0; i < 4; i++) {
            int o = tid + i * NTHR;      // 0..2047
            int r = o >> 3, cc = o & 7;  // row, 16B chunk within row
            const __half* src = (ks < DD)
                ? g_wh + ((size_t)(bm0 + r) * TT + tt) * DD + ks + cc * 8
                : hinp + (size_t)(bm0 + r) * HH + (ks - DD) + cc * 8;
            cp16(ab + r * (A_ROW_H * 2) + cc * 16, src);
        }
        cp_commit();
    };

    for (int t = 0; t < TT; t++) {
        const __half* hin = g_hbuf[t & 1];
        __half* hout = g_hbuf[(t + 1) & 1];

        // chunk 0 already prefetched during previous step's tail (t>0)
        if (t == 0) load_chunk(0, 0, hin);

        float acc[2][4][4];
#pragma unroll
        for (int i = 0; i < 2; i++)
#pragma unroll
            for (int j = 0; j < 4; j++)
#pragma unroll
                for (int r = 0; r < 4; r++) acc[i][j][r] = 0.f;

        for (int c = 0; c < NKT; c++) {
            cp_wait<0>();        // chunk c resident (only group outstanding)
            __syncthreads();
            // issue chunk c+1 into the opposite stage (chunk c-1's, consumed).
            // first h-dependent chunk (2) issued at c==1: wait for all
            // producers of h[t-1] here, hidden under chunk-0 compute.
            if (c + 1 < NKT) {
                if (c == 1 && t > 0) {
                    if (tid == 0)
                        while (ld_acq(&g_sync[mb]) < 64u * (unsigned)t) {}
                    __syncthreads();
                }
                load_chunk(t, c + 1, hin);
            }

            uint32_t ab = a_base + (uint32_t)(c & 1) * A_STAGE_BYTES + a_lane_off;
            uint32_t bb = b_lane_base + c * 128;  // 64 cols * 2B per chunk
#pragma unroll
            for (int kk = 0; kk < 4; kk++) {
                uint32_t af[2][4], bf[4][2];
#pragma unroll
                for (int mt = 0; mt < 2; mt++)
                    ldsm4(af[mt][0], af[mt][1], af[mt][2], af[mt][3],
                          ab + mt * (16 * A_ROW_H * 2) + kk * 32);
#pragma unroll
                for (int p = 0; p < 2; p++)
                    ldsm4(bf[2 * p][0], bf[2 * p][1], bf[2 * p + 1][0], bf[2 * p + 1][1],
                          bb + p * (16 * B_ROW_H * 2) + kk * 32);
#pragma unroll
                for (int mt = 0; mt < 2; mt++)
#pragma unroll
                    for (int nt = 0; nt < 4; nt++)
                        asm volatile(
                            "mma.sync.aligned.m16n8k16.row.col.f32.f16.f16.f32 "
                            "{%0,%1,%2,%3}, {%4,%5,%6,%7}, {%8,%9}, {%0,%1,%2,%3};"
                            : "+f"(acc[mt][nt][0]), "+f"(acc[mt][nt][1]),
                              "+f"(acc[mt][nt][2]), "+f"(acc[mt][nt][3])
                            : "r"(af[mt][0]), "r"(af[mt][1]), "r"(af[mt][2]), "r"(af[mt][3]),
                              "r"(bf[nt][0]), "r"(bf[nt][1]));
            }
        }
        __syncthreads();  // all MMA fragment reads done; A ring reusable as S

        // ---- epilogue phase 1: stage gates to smem (fp32) -------------------
#pragma unroll
        for (int mt = 0; mt < 2; mt++) {
            int r0 = wm * 32 + mt * 16 + (lane >> 2);
#pragma unroll
            for (int nt = 0; nt < 4; nt++) {
                int c0 = wn * 32 + nt * 8 + ((lane & 3) << 1);
                *(float2*)&S[r0 * EPI_STRIDE + c0] =
                    make_float2(acc[mt][nt][0], acc[mt][nt][1]);
                *(float2*)&S[(r0 + 8) * EPI_STRIDE + c0] =
                    make_float2(acc[mt][nt][2], acc[mt][nt][3]);
            }
        }
        __syncthreads();

        // ---- epilogue phase 2: LSTM update (c in regs), store h first -------
        float hnv[8];
#pragma unroll
        for (int i = 0; i < 8; i++) {
            int row = (tid >> 4) + i * 32;
            float4 g = *(const float4*)&S[row * EPI_STRIDE + 4 * u];
            float si = sigmoid_fast(g.x + bi.x);
            float sf = sigmoid_fast(g.y + bi.y);
            float gg = tanh_fast(g.z + bi.z);
            float so = sigmoid_fast(g.w + bi.w);
            float cn = sf * creg[i] + si * gg;
            float hn = so * tanh_fast(cn);
            creg[i] = cn;
            hnv[i] = hn;
            hout[(size_t)(bm0 + row) * HH + U] = __float2half_rn(hn);
        }

        // ---- early arrive (release atomic) + cross-step prefetch -------------
        if (t + 1 < TT) {
            __syncthreads();   // all h writes issued; ALL S reads done
            if (tid == 0) red_release_add(&g_sync[mb], 1u);
            // prefetch next step's w-chunk 0 into stage 0 (safe: S reads done);
            // overlaps output stores + other CTAs' arrivals.
            load_chunk(t + 1, 0, hin);
        }
#pragma unroll
        for (int i = 0; i < 8; i++) {
            int row = (tid >> 4) + i * 32;
            outh[((size_t)(bm0 + row) * TT + t) * HH + U] = hnv[i];
        }
    }
}

// ---------------- launch ----------------------------------------------------
extern "C" void kernel_launch(void* const* d_in, const int* in_sizes, int n_in,
                              void* d_out, int out_size) {
    (void)in_sizes; (void)n_in; (void)out_size;
    const float* x     = (const float*)d_in[0];
    const float* wattn = (const float*)d_in[1];
    // d_in[2] = b_attn: irrelevant (softmax shift invariance)
    const float* wih   = (const float*)d_in[3];
    const float* whh   = (const float*)d_in[4];
    const float* bih   = (const float*)d_in[5];
    const float* bhh   = (const float*)d_in[6];

    float* out  = (float*)d_out;
    float* outw = out;                               // (B, T, D)
    float* outh = out + (size_t)BB * TT * DD;        // (B, T, H)

    cudaFuncSetAttribute(persistent_lstm, cudaFuncAttributeMaxDynamicSharedMemorySize,
                         SMEM_TOTAL);

    attn_weight_kernel<<<BB, DD>>>(x, wattn, outw);
    prep_kernel<<<2048, 256>>>(wih, whh, bih, bhh);
    zero_kernel<<<(BB * HH + 255) / 256, 256>>>();

    persistent_lstm<<<NCTA, NTHR, SMEM_TOTAL>>>(outh);
}

// round 17
// speedup vs baseline: 1.5561x; 1.3798x over previous
#include <cuda_runtime.h>
#include <cuda_fp16.h>
#include <cstdint>
#include <math.h>

#define BB 512
#define TT 255
#define DD 128
#define HH 1024
#define GG 4096   // 4*H
#define KC 1152   // D + H
#define NKT 18    // KC/64

#define NCTA 128      // 64 N-blocks x 2 M-blocks, all co-resident
#define MT 256        // M tile
#define NT 64         // N tile
#define NTHR 512      // 16 warps: 2 N-groups x 8 M-groups (4 warps/SMSP)

// smem geometry
#define B_ROW_H 1160                          // 1152 + 8 pad halves (stride 2320B = 1 mod 8 slots)
#define B_BYTES (NT * B_ROW_H * 2)            // 148480
#define A_ROW_H 72                            // 64 + 8 pad halves (stride 144B = 1 mod 8 slots)
#define A_STAGE_BYTES (MT * A_ROW_H * 2)      // 36864
#define STAGES 2
#define SMEM_TOTAL (B_BYTES + STAGES * A_STAGE_BYTES)  // 222208
#define EPI_STRIDE 68                         // fp32 gate staging stride (floats)
// S = 256 x 68 floats = 69632 B fits the 2-stage A ring (73728 B). The
// cross-step prefetch (chunk 0 -> stage 0) is issued only AFTER the last S
// read (guarded by the early-arrive __syncthreads). Stage map: chunk c -> c&1.
// K-loop sync is PER WM-PAIR (named barriers 1..8): pair wm loads and consumes
// only A rows wm*32..wm*32+31, so no cross-pair smem dependency inside the
// K-loop. Block-wide syncs only at K-loop end + epilogue (S spans all pairs).

// ---------------- scratch (device globals: no allocation allowed) ----------
__device__ __align__(16) __half g_wh[(size_t)BB * TT * DD];   // w = a*x fp16
__device__ __align__(16) __half g_hbuf[2][BB * HH];           // h ping-pong fp16
__device__ __align__(16) __half g_wcat[(size_t)GG * KC];      // permuted weights fp16
__device__ __align__(16) float  g_bias[GG];                   // permuted bias
__device__ unsigned g_sync[2];                // per-M-group monotonic step counter

__device__ __forceinline__ void cp16(uint32_t smem_dst, const void* gmem_src) {
    asm volatile("cp.async.cg.shared.global [%0], [%1], 16;\n" :: "r"(smem_dst), "l"(gmem_src));
}
__device__ __forceinline__ void cp_commit() { asm volatile("cp.async.commit_group;\n"); }
template <int N> __device__ __forceinline__ void cp_wait() {
    asm volatile("cp.async.wait_group %0;\n" :: "n"(N));
}
__device__ __forceinline__ void bar_pair(int id) {
    asm volatile("bar.sync %0, 64;" :: "r"(id) : "memory");
}
__device__ __forceinline__ uint32_t smem_u32(const void* p) {
    uint32_t a;
    asm("{ .reg .u64 t; cvta.to.shared.u64 t, %1; cvt.u32.u64 %0, t; }" : "=r"(a) : "l"(p));
    return a;
}
__device__ __forceinline__ void ldsm4(uint32_t& r0, uint32_t& r1, uint32_t& r2, uint32_t& r3,
                                      uint32_t addr) {
    asm volatile("ldmatrix.sync.aligned.m8n8.x4.shared.b16 {%0,%1,%2,%3}, [%4];"
                 : "=r"(r0), "=r"(r1), "=r"(r2), "=r"(r3) : "r"(addr));
}
__device__ __forceinline__ float tanh_fast(float x) {
    float y;
    asm("tanh.approx.f32 %0, %1;" : "=f"(y) : "f"(x));
    return y;
}
__device__ __forceinline__ float sigmoid_fast(float x) {
    // sigma(x) = 0.5*tanh(x/2) + 0.5  -> single MUFU op
    return fmaf(0.5f, tanh_fast(0.5f * x), 0.5f);
}
__device__ __forceinline__ unsigned ld_acq(const unsigned* p) {
    unsigned v;
    asm volatile("ld.acquire.gpu.global.u32 %0, [%1];" : "=r"(v) : "l"(p));
    return v;
}
__device__ __forceinline__ void red_release_add(unsigned* p, unsigned v) {
    asm volatile("red.release.gpu.global.add.u32 [%0], %1;" :: "l"(p), "r"(v) : "memory");
}

// ---------------- kernel 1: fused e_x + softmax + w = a*x -------------------
__global__ void attn_weight_kernel(const float* __restrict__ x,
                                   const float* __restrict__ wattn,
                                   float* __restrict__ outw) {
    int b = blockIdx.x, d = threadIdx.x;  // 128 threads
    __shared__ float swx[TT];
    __shared__ float red[8];
    for (int i = d; i < TT; i += DD) swx[i] = wattn[2 * HH + i];
    __syncthreads();
    const float* xb = x + (size_t)b * TT * DD + d;
    float e = 0.f;
#pragma unroll 5
    for (int t = 0; t < TT; t++) e += xb[(size_t)t * DD] * swx[t];
    int lane = d & 31, warp = d >> 5;
    float m = e;
#pragma unroll
    for (int o = 16; o; o >>= 1) m = fmaxf(m, __shfl_xor_sync(0xffffffffu, m, o));
    if (!lane) red[warp] = m;
    __syncthreads();
    m = fmaxf(fmaxf(red[0], red[1]), fmaxf(red[2], red[3]));
    float ex = expf(e - m);
    float s = ex;
#pragma unroll
    for (int o = 16; o; o >>= 1) s += __shfl_xor_sync(0xffffffffu, s, o);
    if (!lane) red[4 + warp] = s;
    __syncthreads();
    s = red[4] + red[5] + red[6] + red[7];
    float a = ex / s;

    float* ob = outw + (size_t)b * TT * DD + d;
    __half* hb = g_wh + (size_t)b * TT * DD + d;
#pragma unroll 5
    for (int t = 0; t < TT; t++) {
        float w = a * xb[(size_t)t * DD];
        ob[(size_t)t * DD] = w;
        hb[(size_t)t * DD] = __float2half_rn(w);
    }
}

// ---------------- kernel 2: permuted fp16 weights + bias --------------------
// output col n <-> gate row r = (n&3)*H + (n>>2): 4-col groups = (i,f,g,o) quads
__global__ void prep_kernel(const float* __restrict__ wih, const float* __restrict__ whh,
                            const float* __restrict__ bih, const float* __restrict__ bhh) {
    size_t n = (size_t)GG * KC;
    size_t tid0 = (size_t)blockIdx.x * blockDim.x + threadIdx.x;
    for (size_t i = tid0; i < n; i += (size_t)gridDim.x * blockDim.x) {
        int k = (int)(i % KC);
        int nn = (int)(i / KC);
        int r = (nn & 3) * HH + (nn >> 2);
        float v = (k < DD) ? wih[(size_t)r * DD + k] : whh[(size_t)r * HH + (k - DD)];
        g_wcat[i] = __float2half_rn(v);
    }
    if (tid0 < GG) {
        int r = ((int)tid0 & 3) * HH + ((int)tid0 >> 2);
        g_bias[tid0] = bih[r] + bhh[r];
    }
}

// ---------------- kernel 3: zero h0, sync counters ---------------------------
__global__ void zero_kernel() {
    int i = blockIdx.x * blockDim.x + threadIdx.x;
    if (i < BB * HH) g_hbuf[0][i] = __float2half(0.f);
    if (i < 2) g_sync[i] = 0;
}

// ---------------- kernel 4: persistent fused LSTM ---------------------------
// 128 CTAs x 512 threads (2N x 8M); B resident; 64-wide K-chunks with
// PER-PAIR pipelines (named barriers, no block sync in K-loop); c-state in
// registers; tail prefetch; release-atomic arrive / acquire-spin late wait.
__global__ __launch_bounds__(NTHR, 1) void persistent_lstm(float* __restrict__ outh) {
    extern __shared__ char smraw[];
    float* S = (float*)(smraw + B_BYTES);          // epilogue staging (A ring)
    uint32_t smem_base = smem_u32(smraw);
    uint32_t a_base = smem_base + B_BYTES;

    int tid = threadIdx.x;
    int warp = tid >> 5, lane = tid & 31;
    int wn = warp & 1, wm = warp >> 1;             // 2 warps N x 8 warps M
    int ptid = tid & 63;                           // thread index within wm-pair
    int bar_id = wm + 1;                           // named barrier (1..8; 0 = __syncthreads)
    int bx = blockIdx.x;
    int mb = bx >> 6, nb = bx & 63;
    int bm0 = mb * MT, bn0 = nb * NT;

    // ---- load resident B slab: 64 x 1152 halves (all threads) ---------------
    for (int i = tid; i < NT * (KC / 8); i += NTHR) {
        int n = i / (KC / 8), kc = i % (KC / 8);
        cp16(smem_base + n * (B_ROW_H * 2) + kc * 16,
             g_wcat + (size_t)(bn0 + n) * KC + kc * 8);
    }
    cp_commit();
    cp_wait<0>();
    __syncthreads();   // B fully resident for all warps before any B ldsm

    // ---- per-thread ldmatrix lane offsets (bytes) ----------------------------
    int arow = (lane & 7) + ((lane >> 3) & 1) * 8;
    int acol = ((lane >> 4) & 1) * 8;
    uint32_t a_lane_off = (uint32_t)(((wm * 32 + arow) * A_ROW_H + acol) * 2);
    int brow = (lane & 7) + ((lane >> 4) & 1) * 8;
    int bcol = ((lane >> 3) & 1) * 8;
    uint32_t b_lane_base = smem_base + (uint32_t)(((wn * 32 + brow) * B_ROW_H + bcol) * 2);

    // ---- LSTM c-state in registers; per-thread constants ---------------------
    float creg[8];
#pragma unroll
    for (int i = 0; i < 8; i++) creg[i] = 0.f;
    int u = tid & 15;
    int U = nb * 16 + u;
    float4 bi = *(const float4*)&g_bias[bn0 + 4 * u];   // step-invariant

    // per-pair A chunk loader: pair wm loads ITS 32 rows (4 KB) of the chunk.
    // 64 threads x 4 cp16 = 256 x 16B = 32 rows x 128 B.
    auto load_chunk = [&](int tt, int c, const __half* hinp) {
        int ks = c * 64;
        uint32_t ab = a_base + (uint32_t)(c & 1) * A_STAGE_BYTES;
#pragma unroll
        for (int i = 0; i < 4; i++) {
            int o = ptid + i * 64;       // 0..255
            int rl = o >> 3, cc = o & 7; // local row (0..31), 16B chunk in row
            int r = wm * 32 + rl;
            const __half* src = (ks < DD)
                ? g_wh + ((size_t)(bm0 + r) * TT + tt) * DD + ks + cc * 8
                : hinp + (size_t)(bm0 + r) * HH + (ks - DD) + cc * 8;
            cp16(ab + r * (A_ROW_H * 2) + cc * 16, src);
        }
        cp_commit();
    };

    for (int t = 0; t < TT; t++) {
        const __half* hin = g_hbuf[t & 1];
        __half* hout = g_hbuf[(t + 1) & 1];

        // chunk 0 already prefetched during previous step's tail (t>0)
        if (t == 0) load_chunk(0, 0, hin);

        float acc[2][4][4];
#pragma unroll
        for (int i = 0; i < 2; i++)
#pragma unroll
            for (int j = 0; j < 4; j++)
#pragma unroll
                for (int r = 0; r < 4; r++) acc[i][j][r] = 0.f;

        for (int c = 0; c < NKT; c++) {
            cp_wait<0>();        // own cp.async groups drained (chunk c half)
            bar_pair(bar_id);    // partner's half of this pair's rows resident
            // issue chunk c+1 into the opposite stage (pair's own rows only).
            // first h-dependent chunk (2) issued at c==1: one thread per pair
            // waits for all producers of h[t-1], hidden under chunk-0 compute.
            if (c + 1 < NKT) {
                if (c == 1 && t > 0) {
                    if (ptid == 0)
                        while (ld_acq(&g_sync[mb]) < 64u * (unsigned)t) {}
                    bar_pair(bar_id);
                }
                load_chunk(t, c + 1, hin);
            }

            uint32_t ab = a_base + (uint32_t)(c & 1) * A_STAGE_BYTES + a_lane_off;
            uint32_t bb = b_lane_base + c * 128;  // 64 cols * 2B per chunk
#pragma unroll
            for (int kk = 0; kk < 4; kk++) {
                uint32_t af[2][4], bf[4][2];
#pragma unroll
                for (int mt = 0; mt < 2; mt++)
                    ldsm4(af[mt][0], af[mt][1], af[mt][2], af[mt][3],
                          ab + mt * (16 * A_ROW_H * 2) + kk * 32);
#pragma unroll
                for (int p = 0; p < 2; p++)
                    ldsm4(bf[2 * p][0], bf[2 * p][1], bf[2 * p + 1][0], bf[2 * p + 1][1],
                          bb + p * (16 * B_ROW_H * 2) + kk * 32);
#pragma unroll
                for (int mt = 0; mt < 2; mt++)
#pragma unroll
                    for (int nt = 0; nt < 4; nt++)
                        asm volatile(
                            "mma.sync.aligned.m16n8k16.row.col.f32.f16.f16.f32 "
                            "{%0,%1,%2,%3}, {%4,%5,%6,%7}, {%8,%9}, {%0,%1,%2,%3};"
                            : "+f"(acc[mt][nt][0]), "+f"(acc[mt][nt][1]),
                              "+f"(acc[mt][nt][2]), "+f"(acc[mt][nt][3])
                            : "r"(af[mt][0]), "r"(af[mt][1]), "r"(af[mt][2]), "r"(af[mt][3]),
                              "r"(bf[nt][0]), "r"(bf[nt][1]));
            }
        }
        __syncthreads();  // ALL pairs' MMA frag reads done; A ring reusable as S

        // ---- epilogue phase 1: stage gates to smem (fp32) -------------------
#pragma unroll
        for (int mt = 0; mt < 2; mt++) {
            int r0 = wm * 32 + mt * 16 + (lane >> 2);
#pragma unroll
            for (int nt = 0; nt < 4; nt++) {
                int c0 = wn * 32 + nt * 8 + ((lane & 3) << 1);
                *(float2*)&S[r0 * EPI_STRIDE + c0] =
                    make_float2(acc[mt][nt][0], acc[mt][nt][1]);
                *(float2*)&S[(r0 + 8) * EPI_STRIDE + c0] =
                    make_float2(acc[mt][nt][2], acc[mt][nt][3]);
            }
        }
        __syncthreads();

        // ---- epilogue phase 2: LSTM update (c in regs), store h first -------
        float hnv[8];
#pragma unroll
        for (int i = 0; i < 8; i++) {
            int row = (tid >> 4) + i * 32;
            float4 g = *(const float4*)&S[row * EPI_STRIDE + 4 * u];
            float si = sigmoid_fast(g.x + bi.x);
            float sf = sigmoid_fast(g.y + bi.y);
            float gg = tanh_fast(g.z + bi.z);
            float so = sigmoid_fast(g.w + bi.w);
            float cn = sf * creg[i] + si * gg;
            float hn = so * tanh_fast(cn);
            creg[i] = cn;
            hnv[i] = hn;
            hout[(size_t)(bm0 + row) * HH + U] = __float2half_rn(hn);
        }

        // ---- early arrive (release atomic) + cross-step prefetch -------------
        if (t + 1 < TT) {
            __syncthreads();   // all h writes issued; ALL S reads done
            if (tid == 0) red_release_add(&g_sync[mb], 1u);
            // prefetch next step's w-chunk 0 into stage 0 (safe: S reads done);
            // overlaps output stores + other CTAs' arrivals.
            load_chunk(t + 1, 0, hin);
        }
#pragma unroll
        for (int i = 0; i < 8; i++) {
            int row = (tid >> 4) + i * 32;
            outh[((size_t)(bm0 + row) * TT + t) * HH + U] = hnv[i];
        }
    }
}

// ---------------- launch ----------------------------------------------------
extern "C" void kernel_launch(void* const* d_in, const int* in_sizes, int n_in,
                              void* d_out, int out_size) {
    (void)in_sizes; (void)n_in; (void)out_size;
    const float* x     = (const float*)d_in[0];
    const float* wattn = (const float*)d_in[1];
    // d_in[2] = b_attn: irrelevant (softmax shift invariance)
    const float* wih   = (const float*)d_in[3];
    const float* whh   = (const float*)d_in[4];
    const float* bih   = (const float*)d_in[5];
    const float* bhh   = (const float*)d_in[6];

    float* out  = (float*)d_out;
    float* outw = out;                               // (B, T, D)
    float* outh = out + (size_t)BB * TT * DD;        // (B, T, H)

    cudaFuncSetAttribute(persistent_lstm, cudaFuncAttributeMaxDynamicSharedMemorySize,
                         SMEM_TOTAL);

    attn_weight_kernel<<<BB, DD>>>(x, wattn, outw);
    prep_kernel<<<2048, 256>>>(wih, whh, bih, bhh);
    zero_kernel<<<(BB * HH + 255) / 256, 256>>>();

    persistent_lstm<<<NCTA, NTHR, SMEM_TOTAL>>>(outh);
}